// round 1
// baseline (speedup 1.0000x reference)
#include <cuda_runtime.h>
#include <math.h>

// Problem constants
#define BB   64
#define SS   1024
#define DD   128
#define HH   256
#define M_ROWS (BB*SS)          // 65536
#define NPROJ  (4*HH)           // 1024
#define N2H    (2*HH)           // 512

// ---------------- device scratch (no allocations allowed) ----------------
__device__ __align__(16) float g_P[(size_t)M_ROWS * NPROJ];     // 256 MB: [xz_f|xh_f|xz_b|xh_b]
__device__ __align__(16) float g_Hout[(size_t)M_ROWS * N2H];    // 128 MB: [h_f|h_b] per (b,s)
__device__ __align__(16) float g_T[(size_t)M_ROWS * N2H];       // 128 MB: tanh(out@W1+b1)
__device__ __align__(16) float g_Wcat[DD * NPROJ];
__device__ __align__(16) float g_bcat[NPROJ];
__device__ __align__(16) float g_Hbuf[2][2][BB * HH];           // double-buffered h per direction
__device__ float g_scores[BB * SS];
__device__ unsigned g_bar_cnt[2];
__device__ volatile unsigned g_bar_gen[2];
__device__ unsigned g_exit_cnt[2];

// ---------------- weight packing ----------------
__global__ void pack_weights(const float* __restrict__ Wzf, const float* __restrict__ Whf,
                             const float* __restrict__ Wzb, const float* __restrict__ Whb,
                             const float* __restrict__ bzf, const float* __restrict__ bhf,
                             const float* __restrict__ bzb, const float* __restrict__ bhb) {
    int idx = blockIdx.x * 256 + threadIdx.x;
    if (idx < DD * NPROJ) {
        int k = idx >> 10;        // / 1024
        int n = idx & 1023;
        int sel = n >> 8;
        int c = n & 255;
        const float* W = (sel == 0) ? Wzf : (sel == 1) ? Whf : (sel == 2) ? Wzb : Whb;
        g_Wcat[idx] = W[k * HH + c];
    }
    if (idx < NPROJ) {
        int sel = idx >> 8;
        int c = idx & 255;
        const float* bp = (sel == 0) ? bzf : (sel == 1) ? bhf : (sel == 2) ? bzb : bhb;
        g_bcat[idx] = bp[c];
    }
}

// ---------------- fp32 SGEMM: C[M x N] = A[M x K] @ B[K x N] + bias, optional tanh ----------------
// CTA tile 128x64, 256 threads, 8x4 per thread, K-chunks of 16.
template<int K, int N, bool ACT>
__device__ __forceinline__ void sgemm_body(const float* __restrict__ A, const float* __restrict__ B,
                                           const float* __restrict__ bias, float* __restrict__ C) {
    __shared__ __align__(16) float As[16][132];
    __shared__ __align__(16) float Bs[16][68];
    const int tx = threadIdx.x;
    const int m0 = blockIdx.x * 128;
    const int n0 = blockIdx.y * 64;
    const int rg = tx >> 4;      // 0..15 -> rows rg*8..rg*8+7
    const int cg = tx & 15;      // 0..15 -> cols cg*4..cg*4+3

    float acc[8][4];
#pragma unroll
    for (int r = 0; r < 8; ++r)
#pragma unroll
        for (int c = 0; c < 4; ++c) acc[r][c] = 0.f;

    for (int kc = 0; kc < K; kc += 16) {
        // load A tile 128x16 (512 float4, 2 per thread), store transposed As[k][m]
#pragma unroll
        for (int i = 0; i < 2; ++i) {
            int f = tx + i * 256;
            int row = f >> 2;
            int kq = (f & 3) * 4;
            float4 v = *(const float4*)&A[(size_t)(m0 + row) * K + kc + kq];
            As[kq + 0][row] = v.x;
            As[kq + 1][row] = v.y;
            As[kq + 2][row] = v.z;
            As[kq + 3][row] = v.w;
        }
        // load B tile 16x64 (256 float4, 1 per thread)
        {
            int krow = tx >> 4;
            int nq = (tx & 15) * 4;
            *(float4*)&Bs[krow][nq] = *(const float4*)&B[(size_t)(kc + krow) * N + n0 + nq];
        }
        __syncthreads();
#pragma unroll
        for (int k = 0; k < 16; ++k) {
            float4 a0 = *(const float4*)&As[k][rg * 8];
            float4 a1 = *(const float4*)&As[k][rg * 8 + 4];
            float4 bb = *(const float4*)&Bs[k][cg * 4];
            float ar[8] = {a0.x, a0.y, a0.z, a0.w, a1.x, a1.y, a1.z, a1.w};
            float br[4] = {bb.x, bb.y, bb.z, bb.w};
#pragma unroll
            for (int r = 0; r < 8; ++r)
#pragma unroll
                for (int c = 0; c < 4; ++c)
                    acc[r][c] = fmaf(ar[r], br[c], acc[r][c]);
        }
        __syncthreads();
    }
    // epilogue
    float4 bv4 = *(const float4*)&bias[n0 + cg * 4];
    float bv[4] = {bv4.x, bv4.y, bv4.z, bv4.w};
#pragma unroll
    for (int r = 0; r < 8; ++r) {
        float v0 = acc[r][0] + bv[0];
        float v1 = acc[r][1] + bv[1];
        float v2 = acc[r][2] + bv[2];
        float v3 = acc[r][3] + bv[3];
        if (ACT) { v0 = tanhf(v0); v1 = tanhf(v1); v2 = tanhf(v2); v3 = tanhf(v3); }
        *(float4*)&C[(size_t)(m0 + rg * 8 + r) * N + n0 + cg * 4] = make_float4(v0, v1, v2, v3);
    }
}

__global__ void __launch_bounds__(256) gemm_proj_kernel(const float* __restrict__ x) {
    sgemm_body<DD, NPROJ, false>(x, g_Wcat, g_bcat, g_P);
}
__global__ void __launch_bounds__(256) gemm_attn_kernel(const float* __restrict__ W1,
                                                        const float* __restrict__ b1) {
    sgemm_body<N2H, N2H, true>(g_Hout, W1, b1, g_T);
}

// ---------------- persistent recurrence kernel ----------------
// 128 CTAs: dir = cta>>6, column-group g = cta&63 owns hidden cols [g*4, g*4+4).
// 256 threads: thread = (b = tid>>2, j = tid&3).
__global__ void __launch_bounds__(256, 1) gru_kernel(const float* __restrict__ Uzf,
                                                     const float* __restrict__ Uhf,
                                                     const float* __restrict__ Uzb,
                                                     const float* __restrict__ Uhb) {
    __shared__ __align__(16) float sUz[4][260];
    __shared__ __align__(16) float sUh[4][260];
    __shared__ __align__(16) float shc[2][64][68];

    const int cta = blockIdx.x;
    const int dir = cta >> 6;
    const int grp = cta & 63;
    const int c0 = grp * 4;
    const float* Uz = dir ? Uzb : Uzf;
    const float* Uh = dir ? Uhb : Uhf;
    const int tid = threadIdx.x;
    const int b = tid >> 2;
    const int j = tid & 3;

    // load U column slices, transposed: sU[j][k] = U[k][c0+j]
    for (int i = tid; i < 4 * HH; i += 256) {
        int jj = i >> 8;
        int k = i & 255;
        sUz[jj][k] = Uz[k * HH + c0 + jj];
        sUh[jj][k] = Uh[k * HH + c0 + jj];
    }
    __syncthreads();

    float hself = 0.f;
    const int pofs = dir * 512 + c0 + j;

    for (int t = 0; t < SS; ++t) {
        float accz0 = 0.f, accz1 = 0.f, acch0 = 0.f, acch1 = 0.f;
        if (t > 0) {
            const float* hsrc = &g_Hbuf[(t & 1) ^ 1][dir][0];
            // chunk loader via cp.async.cg (L1-bypass: intra-kernel cross-CTA RAW)
#define LOAD_CHUNK(cn, bufidx)                                                          \
            do {                                                                        \
                int kc_ = (cn) * 64;                                                    \
                _Pragma("unroll")                                                       \
                for (int r_ = 0; r_ < 4; ++r_) {                                        \
                    int f_ = tid + r_ * 256;                                            \
                    int bb_ = f_ >> 4;                                                  \
                    int kq_ = (f_ & 15) << 2;                                           \
                    unsigned dst_ = (unsigned)__cvta_generic_to_shared(                 \
                        &shc[bufidx][bb_][kq_]);                                        \
                    asm volatile("cp.async.cg.shared.global [%0], [%1], 16;"            \
                                 :: "r"(dst_), "l"(hsrc + bb_ * HH + kc_ + kq_));       \
                }                                                                       \
            } while (0)

            LOAD_CHUNK(0, 0);
            asm volatile("cp.async.commit_group;" ::: "memory");
#pragma unroll
            for (int c = 0; c < 4; ++c) {
                if (c < 3) {
                    LOAD_CHUNK(c + 1, (c + 1) & 1);
                    asm volatile("cp.async.commit_group;" ::: "memory");
                    asm volatile("cp.async.wait_group 1;" ::: "memory");
                } else {
                    asm volatile("cp.async.wait_group 0;" ::: "memory");
                }
                __syncthreads();
                const float4* hp = (const float4*)&shc[c & 1][b][0];
                const float4* zp = (const float4*)&sUz[j][c * 64];
                const float4* up = (const float4*)&sUh[j][c * 64];
#pragma unroll
                for (int q = 0; q < 16; q += 2) {
                    float4 h4 = hp[q];
                    float4 h5 = hp[q + 1];
                    float4 z4 = zp[q];
                    float4 z5 = zp[q + 1];
                    float4 u4 = up[q];
                    float4 u5 = up[q + 1];
                    accz0 = fmaf(h4.x, z4.x, accz0); accz0 = fmaf(h4.y, z4.y, accz0);
                    accz0 = fmaf(h4.z, z4.z, accz0); accz0 = fmaf(h4.w, z4.w, accz0);
                    accz1 = fmaf(h5.x, z5.x, accz1); accz1 = fmaf(h5.y, z5.y, accz1);
                    accz1 = fmaf(h5.z, z5.z, accz1); accz1 = fmaf(h5.w, z5.w, accz1);
                    acch0 = fmaf(h4.x, u4.x, acch0); acch0 = fmaf(h4.y, u4.y, acch0);
                    acch0 = fmaf(h4.z, u4.z, acch0); acch0 = fmaf(h4.w, u4.w, acch0);
                    acch1 = fmaf(h5.x, u5.x, acch1); acch1 = fmaf(h5.y, u5.y, acch1);
                    acch1 = fmaf(h5.z, u5.z, acch1); acch1 = fmaf(h5.w, u5.w, acch1);
                }
                __syncthreads();
            }
#undef LOAD_CHUNK
        }
        const int ts = dir ? (SS - 1 - t) : t;
        const float* pr = &g_P[((size_t)(b * SS + ts)) * NPROJ + pofs];
        float az = accz0 + accz1 + pr[0];
        float ah = acch0 + acch1 + pr[HH];
        float z = 1.f / (1.f + expf(-az));
        float hc = tanhf(ah);
        float hnew = fmaf(z, hself - hc, hc);    // z*h + (1-z)*hc
        hself = hnew;
        g_Hbuf[t & 1][dir][b * HH + c0 + j] = hnew;
        g_Hout[((size_t)(b * SS + ts)) * N2H + dir * HH + c0 + j] = hnew;

        if (t < SS - 1) {
            __threadfence();
            __syncthreads();
            if (tid == 0) {
                unsigned target = (unsigned)(t + 1);
                unsigned old = atomicAdd(&g_bar_cnt[dir], 1u);
                if (old == target * 64u - 1u) {
                    __threadfence();
                    g_bar_gen[dir] = target;
                } else {
                    while (g_bar_gen[dir] < target) __nanosleep(64);
                }
                __threadfence();
            }
            __syncthreads();
        }
    }
    // exit: last CTA of each direction resets barrier state for the next graph replay
    __syncthreads();
    if (tid == 0) {
        unsigned old = atomicAdd(&g_exit_cnt[dir], 1u);
        if (old == 63u) {
            g_bar_cnt[dir] = 0u;
            g_bar_gen[dir] = 0u;
            g_exit_cnt[dir] = 0u;
            __threadfence();
        }
    }
}

// ---------------- scores: g_scores[row] = dot(g_T[row, :512], w2) + b2 ----------------
__global__ void __launch_bounds__(256) scores_kernel(const float* __restrict__ w2,
                                                     const float* __restrict__ b2) {
    int row = blockIdx.x * 8 + (threadIdx.x >> 5);
    int lane = threadIdx.x & 31;
    const float4* tr = (const float4*)&g_T[(size_t)row * N2H];
    const float4* wr = (const float4*)w2;
    float s = 0.f;
#pragma unroll
    for (int i = lane; i < N2H / 4; i += 32) {
        float4 v = tr[i];
        float4 w = wr[i];
        s += v.x * w.x + v.y * w.y + v.z * w.z + v.w * w.w;
    }
#pragma unroll
    for (int o = 16; o > 0; o >>= 1) s += __shfl_xor_sync(0xffffffffu, s, o);
    if (lane == 0) g_scores[row] = s + b2[0];
}

// ---------------- softmax over S + weighted context sum ----------------
__global__ void __launch_bounds__(256) softmax_ctx_kernel(float* __restrict__ out) {
    __shared__ float sp[SS];
    __shared__ float rbuf[256];
    const int b = blockIdx.x;
    const int tid = threadIdx.x;

    float mx = -1e30f;
    for (int i = tid; i < SS; i += 256) {
        float v = g_scores[b * SS + i];
        sp[i] = v;
        mx = fmaxf(mx, v);
    }
    rbuf[tid] = mx;
    __syncthreads();
#pragma unroll
    for (int o = 128; o > 0; o >>= 1) {
        if (tid < o) rbuf[tid] = fmaxf(rbuf[tid], rbuf[tid + o]);
        __syncthreads();
    }
    float m = rbuf[0];
    __syncthreads();

    float sum = 0.f;
    for (int i = tid; i < SS; i += 256) {
        float e = expf(sp[i] - m);
        sp[i] = e;
        sum += e;
    }
    rbuf[tid] = sum;
    __syncthreads();
#pragma unroll
    for (int o = 128; o > 0; o >>= 1) {
        if (tid < o) rbuf[tid] += rbuf[tid + o];
        __syncthreads();
    }
    float inv = 1.f / rbuf[0];
    __syncthreads();
    for (int i = tid; i < SS; i += 256) sp[i] *= inv;
    __syncthreads();

    const float* hb = &g_Hout[(size_t)b * SS * N2H];
    float c0 = 0.f, c1 = 0.f, c2 = 0.f, c3 = 0.f;
    for (int s = 0; s < SS; s += 2) {
        float p0 = sp[s];
        float p1 = sp[s + 1];
        c0 = fmaf(p0, hb[(size_t)s * N2H + tid], c0);
        c1 = fmaf(p0, hb[(size_t)s * N2H + HH + tid], c1);
        c2 = fmaf(p1, hb[(size_t)(s + 1) * N2H + tid], c2);
        c3 = fmaf(p1, hb[(size_t)(s + 1) * N2H + HH + tid], c3);
    }
    out[b * N2H + tid] = c0 + c2;
    out[b * N2H + HH + tid] = c1 + c3;
}

// ---------------- launcher ----------------
extern "C" void kernel_launch(void* const* d_in, const int* in_sizes, int n_in,
                              void* d_out, int out_size) {
    const float* x   = (const float*)d_in[0];
    const float* Wzf = (const float*)d_in[1];
    const float* Uzf = (const float*)d_in[2];
    const float* bzf = (const float*)d_in[3];
    const float* Whf = (const float*)d_in[4];
    const float* Uhf = (const float*)d_in[5];
    const float* bhf = (const float*)d_in[6];
    const float* Wzb = (const float*)d_in[7];
    const float* Uzb = (const float*)d_in[8];
    const float* bzb = (const float*)d_in[9];
    const float* Whb = (const float*)d_in[10];
    const float* Uhb = (const float*)d_in[11];
    const float* bhb = (const float*)d_in[12];
    const float* W1  = (const float*)d_in[13];
    const float* b1  = (const float*)d_in[14];
    const float* w2  = (const float*)d_in[15];
    const float* b2  = (const float*)d_in[16];
    float* out = (float*)d_out;

    pack_weights<<<512, 256>>>(Wzf, Whf, Wzb, Whb, bzf, bhf, bzb, bhb);
    gemm_proj_kernel<<<dim3(M_ROWS / 128, NPROJ / 64), 256>>>(x);
    gru_kernel<<<128, 256>>>(Uzf, Uhf, Uzb, Uhb);
    gemm_attn_kernel<<<dim3(M_ROWS / 128, N2H / 64), 256>>>(W1, b1);
    scores_kernel<<<M_ROWS / 8, 256>>>(w2, b2);
    softmax_ctx_kernel<<<BB, 256>>>(out);
}

// round 3
// speedup vs baseline: 2.5737x; 2.5737x over previous
#include <cuda_runtime.h>
#include <math.h>
#include <stdint.h>

// Problem constants
#define BB   64
#define SS   1024
#define DD   128
#define HH   256
#define M_ROWS (BB*SS)          // 65536
#define NPROJ  (4*HH)           // 1024
#define N2H    (2*HH)           // 512

// ---------------- device scratch ----------------
__device__ __align__(16) float g_P[(size_t)M_ROWS * NPROJ];     // 256 MB [xz_f|xh_f|xz_b|xh_b]
__device__ __align__(16) float g_Hout[(size_t)M_ROWS * N2H];    // 128 MB [h_f|h_b]
__device__ __align__(16) float g_Wcat[DD * NPROJ];
__device__ __align__(16) float g_bcat[NPROJ];
__device__ __align__(16) float g_spart[4 * M_ROWS];             // per-n-tile score partials
__device__ __align__(16) float g_attn[M_ROWS];                  // softmax weights
__device__ __align__(16) float g_cpart[8 * BB * N2H];           // context partials

// fast activations (err ~1e-6, fine vs 1e-3 budget)
__device__ __forceinline__ float fast_sigmoid(float x) {
    return __fdividef(1.f, 1.f + __expf(-x));
}
__device__ __forceinline__ float fast_tanh(float x) {
    return 1.f - __fdividef(2.f, __expf(2.f * x) + 1.f);
}

// ---------------- weight packing ----------------
__global__ void pack_weights(const float* __restrict__ Wzf, const float* __restrict__ Whf,
                             const float* __restrict__ Wzb, const float* __restrict__ Whb,
                             const float* __restrict__ bzf, const float* __restrict__ bhf,
                             const float* __restrict__ bzb, const float* __restrict__ bhb) {
    int idx = blockIdx.x * 256 + threadIdx.x;
    if (idx < DD * NPROJ) {
        int k = idx >> 10;
        int n = idx & 1023;
        int sel = n >> 8;
        int c = n & 255;
        const float* W = (sel == 0) ? Wzf : (sel == 1) ? Whf : (sel == 2) ? Wzb : Whb;
        g_Wcat[idx] = W[k * HH + c];
    }
    if (idx < NPROJ) {
        int sel = idx >> 8;
        int c = idx & 255;
        const float* bp = (sel == 0) ? bzf : (sel == 1) ? bhf : (sel == 2) ? bzb : bhb;
        g_bcat[idx] = bp[c];
    }
}

// ---------------- 128x128 SGEMM, 256 threads, 8x8/thread ----------------
// MODE 0: C = A@B + bias
// MODE 1: fused scores: spart[by][row] = sum_c tanh(A@B+bias)[row,c] * w2[c]  (no C write)
template<int K, int N, int MODE>
__device__ __forceinline__ void gemm128_body(const float* __restrict__ A, const float* __restrict__ B,
                                             const float* __restrict__ bias, float* __restrict__ C,
                                             const float* __restrict__ w2, float* __restrict__ spart) {
    __shared__ __align__(16) float As[16][132];
    __shared__ __align__(16) float Bs[16][132];
    const int tid = threadIdx.x;
    const int m0 = blockIdx.x * 128;
    const int n0 = blockIdx.y * 128;
    const int tr = tid >> 4;
    const int tc = tid & 15;

    float acc[8][8];
#pragma unroll
    for (int r = 0; r < 8; ++r)
#pragma unroll
        for (int c = 0; c < 8; ++c) acc[r][c] = 0.f;

    for (int kc = 0; kc < K; kc += 16) {
        // A tile 128x16 -> transposed As[k][m]
#pragma unroll
        for (int i = 0; i < 2; ++i) {
            int f = tid + i * 256;
            int row = f >> 2;
            int kq = (f & 3) * 4;
            float4 v = *(const float4*)&A[(size_t)(m0 + row) * K + kc + kq];
            As[kq + 0][row] = v.x;
            As[kq + 1][row] = v.y;
            As[kq + 2][row] = v.z;
            As[kq + 3][row] = v.w;
        }
        // B tile 16x128
#pragma unroll
        for (int i = 0; i < 2; ++i) {
            int f = tid + i * 256;
            int krow = f >> 5;
            int nq = (f & 31) * 4;
            *(float4*)&Bs[krow][nq] = *(const float4*)&B[(size_t)(kc + krow) * N + n0 + nq];
        }
        __syncthreads();
#pragma unroll
        for (int k = 0; k < 16; ++k) {
            float4 a0 = *(const float4*)&As[k][tr * 8];
            float4 a1 = *(const float4*)&As[k][tr * 8 + 4];
            float4 b0 = *(const float4*)&Bs[k][tc * 8];
            float4 b1 = *(const float4*)&Bs[k][tc * 8 + 4];
            float av[8] = {a0.x, a0.y, a0.z, a0.w, a1.x, a1.y, a1.z, a1.w};
            float bv[8] = {b0.x, b0.y, b0.z, b0.w, b1.x, b1.y, b1.z, b1.w};
#pragma unroll
            for (int r = 0; r < 8; ++r)
#pragma unroll
                for (int c = 0; c < 8; ++c)
                    acc[r][c] = fmaf(av[r], bv[c], acc[r][c]);
        }
        __syncthreads();
    }

    float4 bb0 = *(const float4*)&bias[n0 + tc * 8];
    float4 bb1 = *(const float4*)&bias[n0 + tc * 8 + 4];
    float bv[8] = {bb0.x, bb0.y, bb0.z, bb0.w, bb1.x, bb1.y, bb1.z, bb1.w};

    if (MODE == 0) {
#pragma unroll
        for (int r = 0; r < 8; ++r) {
            float4 o0 = make_float4(acc[r][0] + bv[0], acc[r][1] + bv[1],
                                    acc[r][2] + bv[2], acc[r][3] + bv[3]);
            float4 o1 = make_float4(acc[r][4] + bv[4], acc[r][5] + bv[5],
                                    acc[r][6] + bv[6], acc[r][7] + bv[7]);
            float* cp = &C[(size_t)(m0 + tr * 8 + r) * N + n0 + tc * 8];
            *(float4*)cp = o0;
            *(float4*)(cp + 4) = o1;
        }
    } else {
        __shared__ float red[128][17];
        float4 w20 = *(const float4*)&w2[n0 + tc * 8];
        float4 w21 = *(const float4*)&w2[n0 + tc * 8 + 4];
        float wv[8] = {w20.x, w20.y, w20.z, w20.w, w21.x, w21.y, w21.z, w21.w};
#pragma unroll
        for (int r = 0; r < 8; ++r) {
            float s = 0.f;
#pragma unroll
            for (int c = 0; c < 8; ++c)
                s = fmaf(fast_tanh(acc[r][c] + bv[c]), wv[c], s);
            red[tr * 8 + r][tc] = s;
        }
        __syncthreads();
        if (tid < 128) {
            float s = 0.f;
#pragma unroll
            for (int c = 0; c < 16; ++c) s += red[tid][c];
            spart[(size_t)blockIdx.y * M_ROWS + m0 + tid] = s;
        }
    }
}

__global__ void __launch_bounds__(256) gemm_proj_kernel(const float* __restrict__ x) {
    gemm128_body<DD, NPROJ, 0>(x, g_Wcat, g_bcat, g_P, nullptr, nullptr);
}
__global__ void __launch_bounds__(256) gemm_score_kernel(const float* __restrict__ W1,
                                                         const float* __restrict__ b1,
                                                         const float* __restrict__ w2) {
    gemm128_body<N2H, N2H, 1>(g_Hout, W1, b1, nullptr, w2, g_spart);
}

// ---------------- cluster-based recurrence ----------------
// 128 CTAs = 32 clusters of 4. Cluster c: dir = c>>4, batches [(c&15)*4, +4).
// Rank r owns hidden columns [r*64, r*64+64). U slices in smem; h exchanged via DSMEM.
#define USTR 260
#define SM_UZ   0
#define SM_UH   (64 * USTR)
#define SM_H    (2 * 64 * USTR)            // [2][4][256]
#define SM_P    (SM_H + 2048)              // [4][2][4][64] partials
#define SMEM_GRU_FLOATS (SM_P + 2048)
#define SMEM_GRU_BYTES  (SMEM_GRU_FLOATS * 4)

__device__ __forceinline__ void st_cluster_f32(uint32_t addr, uint32_t rank, float v) {
    uint32_t ra;
    asm volatile("mapa.shared::cluster.u32 %0, %1, %2;" : "=r"(ra) : "r"(addr), "r"(rank));
    asm volatile("st.shared::cluster.f32 [%0], %1;" :: "r"(ra), "f"(v) : "memory");
}

__global__ void __launch_bounds__(256, 1) __cluster_dims__(4, 1, 1)
gru_kernel(const float* __restrict__ Uzf, const float* __restrict__ Uhf,
           const float* __restrict__ Uzb, const float* __restrict__ Uhb) {
    extern __shared__ __align__(16) float sm[];
    const int tid = threadIdx.x;
    uint32_t rank;
    asm("mov.u32 %0, %%cluster_ctarank;" : "=r"(rank));
    const int cidx = blockIdx.x >> 2;
    const int dir = cidx >> 4;
    const int b0 = (cidx & 15) * 4;
    const int j0 = (int)rank * 64;
    const float* Uz = dir ? Uzb : Uzf;
    const float* Uh = dir ? Uhb : Uhf;

    float* sUz = sm + SM_UZ;
    float* sUh = sm + SM_UH;
    float* sh  = sm + SM_H;
    float* pp  = sm + SM_P;

    // load U column slices, transposed: sU[j][k] = U[k][j0+j]
    for (int i = tid; i < 64 * 256; i += 256) {
        int k = i >> 6;
        int j = i & 63;
        sUz[j * USTR + k] = Uz[k * HH + j0 + j];
        sUh[j * USTR + k] = Uh[k * HH + j0 + j];
    }
    __syncthreads();

    // k-loop role: tid = ks*64 + kj  (ks = k-quarter, kj = local column)
    const int kj = tid & 63;
    const int ks = tid >> 6;
    // finalize role: tid = fb*64 + fj
    const int fb = tid >> 6;
    const int fj = tid & 63;

    const float4* sUz4 = (const float4*)(sUz + kj * USTR + ks * 64);
    const float4* sUh4 = (const float4*)(sUh + kj * USTR + ks * 64);

    uint32_t sh_u32 = (uint32_t)__cvta_generic_to_shared(sh);
    const uint32_t hoff_base = ((uint32_t)(fb * 256 + j0 + fj)) * 4u;

    float hself = 0.f;

    for (int t = 0; t < SS; ++t) {
        const int ts = dir ? (SS - 1 - t) : t;
        // prefetch input projections (consumed ~1500 cyc later)
        const size_t prow = ((size_t)(b0 + fb) * SS + ts) * NPROJ + dir * 512 + j0 + fj;
        const float xz = g_P[prow];
        const float xh = g_P[prow + HH];

        float az, ah;
        if (t > 0) {
            const float4* hb = (const float4*)(sh + (((t & 1) ^ 1) << 10));
            float a0 = 0.f, a1 = 0.f, a2 = 0.f, a3 = 0.f;
            float c0 = 0.f, c1 = 0.f, c2 = 0.f, c3 = 0.f;
#pragma unroll
            for (int q = 0; q < 16; ++q) {
                float4 uz = sUz4[q];
                float4 uh = sUh4[q];
                int kq = ks * 16 + q;
                float4 h0 = hb[0 * 64 + kq];
                float4 h1 = hb[1 * 64 + kq];
                float4 h2 = hb[2 * 64 + kq];
                float4 h3 = hb[3 * 64 + kq];
                a0 = fmaf(uz.x, h0.x, a0); a0 = fmaf(uz.y, h0.y, a0);
                a0 = fmaf(uz.z, h0.z, a0); a0 = fmaf(uz.w, h0.w, a0);
                a1 = fmaf(uz.x, h1.x, a1); a1 = fmaf(uz.y, h1.y, a1);
                a1 = fmaf(uz.z, h1.z, a1); a1 = fmaf(uz.w, h1.w, a1);
                a2 = fmaf(uz.x, h2.x, a2); a2 = fmaf(uz.y, h2.y, a2);
                a2 = fmaf(uz.z, h2.z, a2); a2 = fmaf(uz.w, h2.w, a2);
                a3 = fmaf(uz.x, h3.x, a3); a3 = fmaf(uz.y, h3.y, a3);
                a3 = fmaf(uz.z, h3.z, a3); a3 = fmaf(uz.w, h3.w, a3);
                c0 = fmaf(uh.x, h0.x, c0); c0 = fmaf(uh.y, h0.y, c0);
                c0 = fmaf(uh.z, h0.z, c0); c0 = fmaf(uh.w, h0.w, c0);
                c1 = fmaf(uh.x, h1.x, c1); c1 = fmaf(uh.y, h1.y, c1);
                c1 = fmaf(uh.z, h1.z, c1); c1 = fmaf(uh.w, h1.w, c1);
                c2 = fmaf(uh.x, h2.x, c2); c2 = fmaf(uh.y, h2.y, c2);
                c2 = fmaf(uh.z, h2.z, c2); c2 = fmaf(uh.w, h2.w, c2);
                c3 = fmaf(uh.x, h3.x, c3); c3 = fmaf(uh.y, h3.y, c3);
                c3 = fmaf(uh.z, h3.z, c3); c3 = fmaf(uh.w, h3.w, c3);
            }
            // partials: pp[ks*512 + m*256 + b*64 + kj]
            pp[ks * 512 +   0 + 0 * 64 + kj] = a0;
            pp[ks * 512 +   0 + 1 * 64 + kj] = a1;
            pp[ks * 512 +   0 + 2 * 64 + kj] = a2;
            pp[ks * 512 +   0 + 3 * 64 + kj] = a3;
            pp[ks * 512 + 256 + 0 * 64 + kj] = c0;
            pp[ks * 512 + 256 + 1 * 64 + kj] = c1;
            pp[ks * 512 + 256 + 2 * 64 + kj] = c2;
            pp[ks * 512 + 256 + 3 * 64 + kj] = c3;
            __syncthreads();
            az = xz;
            ah = xh;
#pragma unroll
            for (int s2 = 0; s2 < 4; ++s2) {
                az += pp[s2 * 512 + fb * 64 + fj];
                ah += pp[s2 * 512 + 256 + fb * 64 + fj];
            }
        } else {
            az = xz;
            ah = xh;
        }

        float z = fast_sigmoid(az);
        float hc = fast_tanh(ah);
        float hnew = fmaf(z, hself - hc, hc);
        hself = hnew;

        // broadcast hnew to all 4 cluster CTAs' h buffer (incl. self)
        uint32_t loff = sh_u32 + ((uint32_t)(t & 1) << 12) + hoff_base;
#pragma unroll
        for (uint32_t r = 0; r < 4; ++r) st_cluster_f32(loff, r, hnew);

        g_Hout[((size_t)(b0 + fb) * SS + ts) * N2H + dir * HH + j0 + fj] = hnew;

        asm volatile("barrier.cluster.arrive.aligned;" ::: "memory");
        asm volatile("barrier.cluster.wait.aligned;" ::: "memory");
    }
}

// ---------------- softmax over S (weights only) ----------------
__global__ void __launch_bounds__(256) softmax_kernel() {
    __shared__ float sp[SS];
    __shared__ float rbuf[256];
    const int b = blockIdx.x;
    const int tid = threadIdx.x;

    float mx = -1e30f;
    for (int i = tid; i < SS; i += 256) {
        int row = b * SS + i;
        float v = g_spart[row] + g_spart[M_ROWS + row] +
                  g_spart[2 * M_ROWS + row] + g_spart[3 * M_ROWS + row];
        sp[i] = v;
        mx = fmaxf(mx, v);
    }
    rbuf[tid] = mx;
    __syncthreads();
#pragma unroll
    for (int o = 128; o > 0; o >>= 1) {
        if (tid < o) rbuf[tid] = fmaxf(rbuf[tid], rbuf[tid + o]);
        __syncthreads();
    }
    float m = rbuf[0];
    __syncthreads();

    float sum = 0.f;
    for (int i = tid; i < SS; i += 256) {
        float e = __expf(sp[i] - m);
        sp[i] = e;
        sum += e;
    }
    rbuf[tid] = sum;
    __syncthreads();
#pragma unroll
    for (int o = 128; o > 0; o >>= 1) {
        if (tid < o) rbuf[tid] += rbuf[tid + o];
        __syncthreads();
    }
    float inv = __fdividef(1.f, rbuf[0]);
    __syncthreads();
    for (int i = tid; i < SS; i += 256) g_attn[b * SS + i] = sp[i] * inv;
}

// ---------------- context: partial over S-chunks, then combine ----------------
__global__ void __launch_bounds__(256) ctx_partial_kernel() {
    const int b = blockIdx.x;
    const int ch = blockIdx.y;       // 8 chunks of 128 timesteps
    const int tid = threadIdx.x;
    const float* hb = &g_Hout[((size_t)b * SS + ch * 128) * N2H];
    const float* ap = &g_attn[b * SS + ch * 128];
    float c0 = 0.f, c1 = 0.f;
    for (int s = 0; s < 128; ++s) {
        float p = ap[s];
        c0 = fmaf(p, hb[(size_t)s * N2H + tid], c0);
        c1 = fmaf(p, hb[(size_t)s * N2H + HH + tid], c1);
    }
    g_cpart[((size_t)ch * BB + b) * N2H + tid] = c0;
    g_cpart[((size_t)ch * BB + b) * N2H + HH + tid] = c1;
}

__global__ void __launch_bounds__(512) ctx_final_kernel(float* __restrict__ out) {
    const int b = blockIdx.x;
    const int tid = threadIdx.x;
    float s = 0.f;
#pragma unroll
    for (int ch = 0; ch < 8; ++ch)
        s += g_cpart[((size_t)ch * BB + b) * N2H + tid];
    out[b * N2H + tid] = s;
}

// ---------------- launcher ----------------
extern "C" void kernel_launch(void* const* d_in, const int* in_sizes, int n_in,
                              void* d_out, int out_size) {
    const float* x   = (const float*)d_in[0];
    const float* Wzf = (const float*)d_in[1];
    const float* Uzf = (const float*)d_in[2];
    const float* bzf = (const float*)d_in[3];
    const float* Whf = (const float*)d_in[4];
    const float* Uhf = (const float*)d_in[5];
    const float* bhf = (const float*)d_in[6];
    const float* Wzb = (const float*)d_in[7];
    const float* Uzb = (const float*)d_in[8];
    const float* bzb = (const float*)d_in[9];
    const float* Whb = (const float*)d_in[10];
    const float* Uhb = (const float*)d_in[11];
    const float* bhb = (const float*)d_in[12];
    const float* W1  = (const float*)d_in[13];
    const float* b1  = (const float*)d_in[14];
    const float* w2  = (const float*)d_in[15];
    float* out = (float*)d_out;

    cudaFuncSetAttribute(gru_kernel, cudaFuncAttributeMaxDynamicSharedMemorySize, SMEM_GRU_BYTES);

    pack_weights<<<512, 256>>>(Wzf, Whf, Wzb, Whb, bzf, bhf, bzb, bhb);
    gemm_proj_kernel<<<dim3(M_ROWS / 128, NPROJ / 128), 256>>>(x);
    gru_kernel<<<128, 256, SMEM_GRU_BYTES>>>(Uzf, Uhf, Uzb, Uhb);
    gemm_score_kernel<<<dim3(M_ROWS / 128, N2H / 128), 256>>>(W1, b1, w2);
    softmax_kernel<<<BB, 256>>>();
    ctx_partial_kernel<<<dim3(BB, 8), 256>>>();
    ctx_final_kernel<<<BB, 512>>>(out);
}